// round 2
// baseline (speedup 1.0000x reference)
#include <cuda_runtime.h>
#include <cuda_bf16.h>
#include <cstdint>

#define NTOT 65536
#define DDIM 512
#define KCL  64

#define BN 128
#define BK 32
#define DTILES 4            // DDIM / BN
#define NCHUNKS 37          // grid = 4 * 37 = 148 CTAs = one full wave
#define KBTOT 2048          // NTOT / BK k-blocks, split 13x56 + 24x55 over chunks
#define SK 34               // padded smem stride (bf16 elems, even -> 4B aligned)
#define NCTAS (DTILES * NCHUNKS)

__device__ float        g_partial[KCL * DDIM];  // .bss zero-init; re-zeroed each call
__device__ float        g_h2sum;
__device__ unsigned int g_count;

struct LdReg { float4 fa, fb, ha0, ha1, hb0, hb1; };

__device__ __forceinline__ uint32_t pack_bf16(float a, float b) {
    __nv_bfloat162 p;
    p.x = __float2bfloat16_rn(a);
    p.y = __float2bfloat16_rn(b);
    return *reinterpret_cast<uint32_t*>(&p);
}

__global__ __launch_bounds__(256, 1)
void k_fused(const float* __restrict__ H, const float* __restrict__ Fm,
             float* __restrict__ out) {
    __shared__ __align__(16) __nv_bfloat16 Fs[3][KCL * SK];
    __shared__ __align__(16) __nv_bfloat16 Hs[3][BN * SK];
    __shared__ float redbuf[8];
    __shared__ unsigned int s_ticket;
    __shared__ double sb[8];

    const int tid  = threadIdx.x;
    const int lane = tid & 31;
    const int wid  = tid >> 5;
    const int d0   = blockIdx.x * BN;
    const int c    = blockIdx.y;

    // 2048 k-blocks over 37 chunks: chunks 0..12 get 56, 13..36 get 55
    const int kb_start = c * 55 + (c < 13 ? c : 13);
    const int ITERS    = 55 + (c < 13 ? 1 : 0);
    const int nb0      = kb_start * BK;

    const int wm = (wid >> 2) * 32;     // warp m-offset (2 warps along m)
    const int wn = (wid & 3) * 32;      // warp n-offset (4 warps along n)
    const int g  = lane >> 2;
    const int t  = lane & 3;

    // global-load task mapping
    const int f_kk  = (tid >> 4) << 1;  // 0,2,..,30
    const int f_m   = (tid & 15) << 2;  // 0,4,..,60
    const int h_kk0 = (tid >> 5) << 1;  // 0..14 even
    const int h_kk1 = h_kk0 + 16;       // 16..30 even
    const int h_n0  = lane << 2;        // 0..124

    float acc[2][4][4];
#pragma unroll
    for (int a = 0; a < 2; a++)
#pragma unroll
        for (int b = 0; b < 4; b++)
#pragma unroll
            for (int cc = 0; cc < 4; cc++) acc[a][b][cc] = 0.f;

    float h2 = 0.f;

    auto gload = [&](LdReg& R, int nb) {
        R.fa  = *(const float4*)&Fm[(size_t)(nb + f_kk)      * KCL  + f_m];
        R.fb  = *(const float4*)&Fm[(size_t)(nb + f_kk + 1)  * KCL  + f_m];
        R.ha0 = *(const float4*)&H [(size_t)(nb + h_kk0)     * DDIM + d0 + h_n0];
        R.ha1 = *(const float4*)&H [(size_t)(nb + h_kk0 + 1) * DDIM + d0 + h_n0];
        R.hb0 = *(const float4*)&H [(size_t)(nb + h_kk1)     * DDIM + d0 + h_n0];
        R.hb1 = *(const float4*)&H [(size_t)(nb + h_kk1 + 1) * DDIM + d0 + h_n0];
    };

    auto sstore = [&](int buf, const LdReg& R) {
        __nv_bfloat16* fs = Fs[buf];
        __nv_bfloat16* hs = Hs[buf];
        const float* pa = &R.fa.x;  const float* pb = &R.fb.x;
#pragma unroll
        for (int j = 0; j < 4; j++)
            *(uint32_t*)&fs[(f_m + j) * SK + f_kk] = pack_bf16(pa[j], pb[j]);
        const float* q0 = &R.ha0.x; const float* q1 = &R.ha1.x;
        const float* r0 = &R.hb0.x; const float* r1 = &R.hb1.x;
#pragma unroll
        for (int j = 0; j < 4; j++) {
            *(uint32_t*)&hs[(h_n0 + j) * SK + h_kk0] = pack_bf16(q0[j], q1[j]);
            *(uint32_t*)&hs[(h_n0 + j) * SK + h_kk1] = pack_bf16(r0[j], r1[j]);
            h2 += q0[j]*q0[j] + q1[j]*q1[j] + r0[j]*r0[j] + r1[j]*r1[j];
        }
    };

    auto compute = [&](int buf) {
        const __nv_bfloat16* fs = Fs[buf];
        const __nv_bfloat16* hs = Hs[buf];
#pragma unroll
        for (int ks = 0; ks < BK; ks += 16) {
            uint32_t a[2][4], b[4][2];
#pragma unroll
            for (int mi = 0; mi < 2; mi++) {
                const __nv_bfloat16* p = &fs[(wm + mi * 16 + g) * SK + ks + 2 * t];
                a[mi][0] = *(const uint32_t*)(p);
                a[mi][1] = *(const uint32_t*)(p + 8 * SK);
                a[mi][2] = *(const uint32_t*)(p + 8);
                a[mi][3] = *(const uint32_t*)(p + 8 * SK + 8);
            }
#pragma unroll
            for (int ni = 0; ni < 4; ni++) {
                const __nv_bfloat16* p = &hs[(wn + ni * 8 + g) * SK + ks + 2 * t];
                b[ni][0] = *(const uint32_t*)(p);
                b[ni][1] = *(const uint32_t*)(p + 8);
            }
#pragma unroll
            for (int mi = 0; mi < 2; mi++)
#pragma unroll
                for (int ni = 0; ni < 4; ni++) {
                    asm volatile(
                        "mma.sync.aligned.m16n8k16.row.col.f32.bf16.bf16.f32 "
                        "{%0,%1,%2,%3}, {%4,%5,%6,%7}, {%8,%9}, {%0,%1,%2,%3};\n"
                        : "+f"(acc[mi][ni][0]), "+f"(acc[mi][ni][1]),
                          "+f"(acc[mi][ni][2]), "+f"(acc[mi][ni][3])
                        : "r"(a[mi][0]), "r"(a[mi][1]), "r"(a[mi][2]), "r"(a[mi][3]),
                          "r"(b[ni][0]), "r"(b[ni][1]));
                }
        }
    };

    // ---- software pipeline: triple smem buffer, prefetch distance 2 ----
    LdReg R[2];
    gload(R[0], nb0);
    gload(R[1], nb0 + BK);
    sstore(0, R[0]);
    __syncthreads();

#pragma unroll 1
    for (int it = 0; it < ITERS; ++it) {
        if (it + 2 < ITERS) gload(R[it & 1], nb0 + (it + 2) * BK);
        compute(it % 3);
        if (it + 1 < ITERS) sstore((it + 1) % 3, R[(it + 1) & 1]);
        __syncthreads();
    }

    // ---- epilogue: packed float2 L2 atomics into partial G ----
#pragma unroll
    for (int mi = 0; mi < 2; mi++)
#pragma unroll
        for (int ni = 0; ni < 4; ni++) {
            int row = wm + mi * 16 + g;
            int col = d0 + wn + ni * 8 + 2 * t;
            atomicAdd((float2*)&g_partial[row * DDIM + col],
                      make_float2(acc[mi][ni][0], acc[mi][ni][1]));
            atomicAdd((float2*)&g_partial[(row + 8) * DDIM + col],
                      make_float2(acc[mi][ni][2], acc[mi][ni][3]));
        }

    // block-reduce h^2, one atomic per CTA
#pragma unroll
    for (int o = 16; o > 0; o >>= 1) h2 += __shfl_xor_sync(0xffffffffu, h2, o);
    if (lane == 0) redbuf[wid] = h2;
    __syncthreads();
    if (tid == 0) {
        float s = 0.f;
#pragma unroll
        for (int w = 0; w < 8; w++) s += redbuf[w];
        atomicAdd(&g_h2sum, s);
    }

    // ---- last-CTA finalize: square-sum G, write scalar, reset state ----
    __threadfence();
    if (tid == 0) s_ticket = atomicAdd(&g_count, 1u);
    __syncthreads();
    if (s_ticket != NCTAS - 1) return;

    double s = 0.0;
    for (int i = tid; i < KCL * DDIM; i += 256) {
        float v = __ldcg(&g_partial[i]);
        s += (double)v * (double)v;
        g_partial[i] = 0.f;                 // re-zero for next graph replay
    }
#pragma unroll
    for (int o = 16; o > 0; o >>= 1) s += __shfl_xor_sync(0xffffffffu, s, o);
    if (lane == 0) sb[wid] = s;
    __syncthreads();
    if (tid == 0) {
        double tot = 0.0;
#pragma unroll
        for (int w = 0; w < 8; w++) tot += sb[w];
        float h2tot = __ldcg(&g_h2sum);
        out[0] = (float)((double)h2tot - tot);
        g_h2sum = 0.f;
        g_count = 0u;
    }
}

extern "C" void kernel_launch(void* const* d_in, const int* in_sizes, int n_in,
                              void* d_out, int out_size) {
    const float* Hp;
    const float* Fp;
    if (in_sizes[0] == NTOT * DDIM) {
        Hp = (const float*)d_in[0];
        Fp = (const float*)d_in[1];
    } else {
        Hp = (const float*)d_in[1];
        Fp = (const float*)d_in[0];
    }

    dim3 grid(DTILES, NCHUNKS);
    k_fused<<<grid, 256>>>(Hp, Fp, (float*)d_out);
}

// round 3
// speedup vs baseline: 1.4248x; 1.4248x over previous
#include <cuda_runtime.h>
#include <cuda_bf16.h>
#include <cstdint>

#define NTOT 65536
#define DDIM 512
#define KCL  64

#define BN 128
#define BK 32
#define DTILES 4            // DDIM / BN
#define NCHUNKS 37          // grid = 4 * 37 = 148 CTAs = one full wave
#define NCTAS (DTILES * NCHUNKS)
#define SK 34               // bf16 tile stride (elems, even -> 4B aligned)

#define STAGES 4
#define SF_STRIDE 72        // f32 per F stage row (64 data + pad, 288B)
#define SH_STRIDE 132       // f32 per H stage row (128 data + pad, 528B)

#define STF_ELEMS (STAGES * 32 * SF_STRIDE)
#define STH_ELEMS (STAGES * 32 * SH_STRIDE)
#define FS_ELEMS  (2 * KCL * SK)
#define HS_ELEMS  (2 * BN * SK)
#define SMEM_BYTES (STF_ELEMS * 4 + STH_ELEMS * 4 + FS_ELEMS * 2 + HS_ELEMS * 2)

__device__ float        g_partial[KCL * DDIM];  // zero-init .bss; re-zeroed per call
__device__ float        g_h2sum;
__device__ unsigned int g_count;

__device__ __forceinline__ uint32_t pack_bf16(float lo, float hi) {
    uint32_t r;
    asm("cvt.rn.bf16x2.f32 %0, %1, %2;" : "=r"(r) : "f"(hi), "f"(lo));
    return r;
}

__device__ __forceinline__ void cp16(void* s, const void* g) {
    uint32_t sa = (uint32_t)__cvta_generic_to_shared(s);
    asm volatile("cp.async.cg.shared.global [%0], [%1], 16;" :: "r"(sa), "l"(g));
}
#define CP_COMMIT() asm volatile("cp.async.commit_group;")
#define CP_WAIT(n)  asm volatile("cp.async.wait_group %0;" :: "n"(n))

__global__ __launch_bounds__(256, 1)
void k_fused(const float* __restrict__ H, const float* __restrict__ Fm,
             float* __restrict__ out) {
    extern __shared__ __align__(16) char smem[];
    float*         stF    = (float*)smem;
    float*         stH    = stF + STF_ELEMS;
    __nv_bfloat16* FsBase = (__nv_bfloat16*)(stH + STH_ELEMS);
    __nv_bfloat16* HsBase = FsBase + FS_ELEMS;

    __shared__ float        redbuf[8];
    __shared__ double       sb[8];
    __shared__ unsigned int s_ticket;

    const int tid  = threadIdx.x;
    const int lane = tid & 31;
    const int wid  = tid >> 5;
    const int d0   = blockIdx.x * BN;
    const int c    = blockIdx.y;

    // 2048 k-blocks over 37 chunks: chunks 0..12 get 56, rest 55
    const int kb_start = c * 55 + (c < 13 ? c : 13);
    const int ITERS    = 55 + (c < 13 ? 1 : 0);
    const int nb0      = kb_start * BK;

    const int wm = (wid >> 2) * 32;
    const int wn = (wid & 3) * 32;
    const int g  = lane >> 2;
    const int t  = lane & 3;

    float acc[2][4][4];
#pragma unroll
    for (int a = 0; a < 2; a++)
#pragma unroll
        for (int b = 0; b < 4; b++)
#pragma unroll
            for (int cc = 0; cc < 4; cc++) acc[a][b][cc] = 0.f;

    float h2 = 0.f;

    // ---- async stage fill: one k-block (BK=32 rows) of F and H, raw f32 ----
    auto issue = [&](int slot, int kb) {
        const int nb = nb0 + kb * BK;
        float* sf = stF + slot * (32 * SF_STRIDE);
        float* sh = stH + slot * (32 * SH_STRIDE);
#pragma unroll
        for (int j = 0; j < 2; j++) {            // F: 512 16B chunks / 256 thr
            int tau = tid + j * 256;
            int r = tau >> 4, ck = tau & 15;
            cp16(sf + r * SF_STRIDE + ck * 4,
                 &Fm[(size_t)(nb + r) * KCL + ck * 4]);
        }
#pragma unroll
        for (int j = 0; j < 4; j++) {            // H: 1024 chunks / 256 thr
            int tau = tid + j * 256;
            int r = tau >> 5, ck = tau & 31;
            cp16(sh + r * SH_STRIDE + ck * 4,
                 &H[(size_t)(nb + r) * DDIM + d0 + ck * 4]);
        }
        CP_COMMIT();
    };

    // ---- convert f32 stage -> bf16 [row][k] tiles (transpose), accumulate h2 ----
    auto convert = [&](int slot, int buf) {
        const float* sf = stF + slot * (32 * SF_STRIDE);
        const float* sh = stH + slot * (32 * SH_STRIDE);
        __nv_bfloat16* fs = FsBase + buf * (KCL * SK);
        __nv_bfloat16* hs = HsBase + buf * (BN * SK);
        {
            int kp = tid >> 4, mq = tid & 15;    // k-pair 0..15, m-quad 0..15
            float4 r0 = *(const float4*)(sf + (2 * kp)     * SF_STRIDE + 4 * mq);
            float4 r1 = *(const float4*)(sf + (2 * kp + 1) * SF_STRIDE + 4 * mq);
            const float* p0 = &r0.x; const float* p1 = &r1.x;
#pragma unroll
            for (int j = 0; j < 4; j++)
                *(uint32_t*)&fs[(4 * mq + j) * SK + 2 * kp] = pack_bf16(p0[j], p1[j]);
        }
#pragma unroll
        for (int jj = 0; jj < 2; jj++) {
            int tau = tid + jj * 256;
            int kp = tau >> 5, dq = tau & 31;    // k-pair 0..15, d-quad 0..31
            float4 r0 = *(const float4*)(sh + (2 * kp)     * SH_STRIDE + 4 * dq);
            float4 r1 = *(const float4*)(sh + (2 * kp + 1) * SH_STRIDE + 4 * dq);
            const float* p0 = &r0.x; const float* p1 = &r1.x;
#pragma unroll
            for (int j = 0; j < 4; j++) {
                *(uint32_t*)&hs[(4 * dq + j) * SK + 2 * kp] = pack_bf16(p0[j], p1[j]);
                h2 += p0[j] * p0[j] + p1[j] * p1[j];
            }
        }
    };

    auto compute = [&](int buf) {
        const __nv_bfloat16* fs = FsBase + buf * (KCL * SK);
        const __nv_bfloat16* hs = HsBase + buf * (BN * SK);
#pragma unroll
        for (int ks = 0; ks < BK; ks += 16) {
            uint32_t a[2][4], b[4][2];
#pragma unroll
            for (int mi = 0; mi < 2; mi++) {
                const __nv_bfloat16* p = &fs[(wm + mi * 16 + g) * SK + ks + 2 * t];
                a[mi][0] = *(const uint32_t*)(p);
                a[mi][1] = *(const uint32_t*)(p + 8 * SK);
                a[mi][2] = *(const uint32_t*)(p + 8);
                a[mi][3] = *(const uint32_t*)(p + 8 * SK + 8);
            }
#pragma unroll
            for (int ni = 0; ni < 4; ni++) {
                const __nv_bfloat16* p = &hs[(wn + ni * 8 + g) * SK + ks + 2 * t];
                b[ni][0] = *(const uint32_t*)(p);
                b[ni][1] = *(const uint32_t*)(p + 8);
            }
#pragma unroll
            for (int mi = 0; mi < 2; mi++)
#pragma unroll
                for (int ni = 0; ni < 4; ni++) {
                    asm volatile(
                        "mma.sync.aligned.m16n8k16.row.col.f32.bf16.bf16.f32 "
                        "{%0,%1,%2,%3}, {%4,%5,%6,%7}, {%8,%9}, {%0,%1,%2,%3};\n"
                        : "+f"(acc[mi][ni][0]), "+f"(acc[mi][ni][1]),
                          "+f"(acc[mi][ni][2]), "+f"(acc[mi][ni][3])
                        : "r"(a[mi][0]), "r"(a[mi][1]), "r"(a[mi][2]), "r"(a[mi][3]),
                          "r"(b[ni][0]), "r"(b[ni][1]));
                }
        }
    };

    // ---- pipeline: 4 async stages in flight, double-buffered bf16 tiles ----
    issue(0, 0); issue(1, 1); issue(2, 2); issue(3, 3);
    CP_WAIT(3);
    __syncthreads();            // stage 0 visible to all threads
    convert(0, 0);

#pragma unroll 1
    for (int it = 0; it < ITERS; ++it) {
        if (it + 1 < ITERS) {
            CP_WAIT(2);         // own groups for stage it+1 done
            __syncthreads();    // everyone's groups done -> stage it+1 visible
            convert((it + 1) & 3, (it + 1) & 1);
        }
        if (it + 4 < ITERS) issue(it & 3, it + 4);   // slot (it+4)&3 == it&3
        __syncthreads();        // bf16 buf(it&1) fully written before compute
        compute(it & 1);
    }

    // ---- epilogue: packed float2 L2 atomics into partial G ----
#pragma unroll
    for (int mi = 0; mi < 2; mi++)
#pragma unroll
        for (int ni = 0; ni < 4; ni++) {
            int row = wm + mi * 16 + g;
            int col = d0 + wn + ni * 8 + 2 * t;
            atomicAdd((float2*)&g_partial[row * DDIM + col],
                      make_float2(acc[mi][ni][0], acc[mi][ni][1]));
            atomicAdd((float2*)&g_partial[(row + 8) * DDIM + col],
                      make_float2(acc[mi][ni][2], acc[mi][ni][3]));
        }

    // block-reduce h2, one atomic per CTA
#pragma unroll
    for (int o = 16; o > 0; o >>= 1) h2 += __shfl_xor_sync(0xffffffffu, h2, o);
    if (lane == 0) redbuf[wid] = h2;
    __syncthreads();
    if (tid == 0) {
        float s = 0.f;
#pragma unroll
        for (int w = 0; w < 8; w++) s += redbuf[w];
        atomicAdd(&g_h2sum, s);
    }

    // ---- last-CTA finalize: square-sum G, write scalar, reset state ----
    __threadfence();
    if (tid == 0) s_ticket = atomicAdd(&g_count, 1u);
    __syncthreads();
    if (s_ticket != NCTAS - 1) return;

    double s = 0.0;
    for (int i = tid; i < KCL * DDIM; i += 256) {
        float v = __ldcg(&g_partial[i]);
        s += (double)v * (double)v;
        g_partial[i] = 0.f;                 // re-zero for next graph replay
    }
#pragma unroll
    for (int o = 16; o > 0; o >>= 1) s += __shfl_xor_sync(0xffffffffu, s, o);
    if (lane == 0) sb[wid] = s;
    __syncthreads();
    if (tid == 0) {
        double tot = 0.0;
#pragma unroll
        for (int w = 0; w < 8; w++) tot += sb[w];
        float h2tot = __ldcg(&g_h2sum);
        out[0] = (float)((double)h2tot - tot);
        g_h2sum = 0.f;
        g_count = 0u;
    }
}

extern "C" void kernel_launch(void* const* d_in, const int* in_sizes, int n_in,
                              void* d_out, int out_size) {
    const float* Hp;
    const float* Fp;
    if (in_sizes[0] == NTOT * DDIM) {
        Hp = (const float*)d_in[0];
        Fp = (const float*)d_in[1];
    } else {
        Hp = (const float*)d_in[1];
        Fp = (const float*)d_in[0];
    }

    cudaFuncSetAttribute(k_fused, cudaFuncAttributeMaxDynamicSharedMemorySize,
                         SMEM_BYTES);
    dim3 grid(DTILES, NCHUNKS);
    k_fused<<<grid, 256, SMEM_BYTES>>>(Hp, Fp, (float*)d_out);
}

// round 4
// speedup vs baseline: 1.7440x; 1.2240x over previous
#include <cuda_runtime.h>
#include <cuda_bf16.h>
#include <cstdint>

#define NTOT 65536
#define DDIM 512
#define KCL  64

#define BN 128
#define BK 32
#define DTILES 4            // DDIM / BN
#define NCHUNKS 74          // grid = 4 * 74 = 296 CTAs = 2 CTAs/SM, one wave
#define NCTAS (DTILES * NCHUNKS)
#define SK 34               // padded smem stride (bf16 elems, even -> 4B aligned)

__device__ float        g_partial[KCL * DDIM];  // .bss zero-init; re-zeroed per call
__device__ float        g_h2sum;
__device__ unsigned int g_count;

__device__ __forceinline__ uint32_t pack_bf16(float lo, float hi) {
    uint32_t r;
    asm("cvt.rn.bf16x2.f32 %0, %1, %2;" : "=r"(r) : "f"(hi), "f"(lo));
    return r;
}

__global__ __launch_bounds__(256, 2)
void k_fused(const float* __restrict__ H, const float* __restrict__ Fm,
             float* __restrict__ out) {
    __shared__ __align__(16) __nv_bfloat16 Fs[2][KCL * SK];
    __shared__ __align__(16) __nv_bfloat16 Hs[2][BN * SK];
    __shared__ float        redbuf[8];
    __shared__ double       sb[8];
    __shared__ unsigned int s_ticket;

    const int tid  = threadIdx.x;
    const int lane = tid & 31;
    const int wid  = tid >> 5;
    const int d0   = blockIdx.x * BN;
    const int c    = blockIdx.y;

    // 2048 k-blocks over 74 chunks: chunks 0..49 get 28, 50..73 get 27
    const int kb_start = c * 27 + (c < 50 ? c : 50);
    const int ITERS    = 27 + (c < 50 ? 1 : 0);
    const int nb0      = kb_start * BK;

    const int wm = (wid >> 2) * 32;     // warp m-offset (2 warps along m)
    const int wn = (wid & 3) * 32;      // warp n-offset (4 warps along n)
    const int g  = lane >> 2;
    const int t  = lane & 3;

    // global-load task mapping (round-1 proven)
    const int f_kk  = (tid >> 4) << 1;  // 0,2,..,30
    const int f_m   = (tid & 15) << 2;  // 0,4,..,60
    const int h_kk0 = (tid >> 5) << 1;  // 0..14 even
    const int h_kk1 = h_kk0 + 16;       // 16..30 even
    const int h_n0  = lane << 2;        // 0..124

    float acc[2][4][4];
#pragma unroll
    for (int a = 0; a < 2; a++)
#pragma unroll
        for (int b = 0; b < 4; b++)
#pragma unroll
            for (int cc = 0; cc < 4; cc++) acc[a][b][cc] = 0.f;

    float h2 = 0.f;

    float4 fa, fb, ha0, ha1, hb0, hb1;

    auto gload = [&](int nb) {
        fa  = *(const float4*)&Fm[(size_t)(nb + f_kk)      * KCL  + f_m];
        fb  = *(const float4*)&Fm[(size_t)(nb + f_kk + 1)  * KCL  + f_m];
        ha0 = *(const float4*)&H [(size_t)(nb + h_kk0)     * DDIM + d0 + h_n0];
        ha1 = *(const float4*)&H [(size_t)(nb + h_kk0 + 1) * DDIM + d0 + h_n0];
        hb0 = *(const float4*)&H [(size_t)(nb + h_kk1)     * DDIM + d0 + h_n0];
        hb1 = *(const float4*)&H [(size_t)(nb + h_kk1 + 1) * DDIM + d0 + h_n0];
    };

    auto sstore = [&](int buf) {
        __nv_bfloat16* fs = Fs[buf];
        __nv_bfloat16* hs = Hs[buf];
        const float* pa = &fa.x;  const float* pb = &fb.x;
#pragma unroll
        for (int j = 0; j < 4; j++)
            *(uint32_t*)&fs[(f_m + j) * SK + f_kk] = pack_bf16(pa[j], pb[j]);
        const float* q0 = &ha0.x; const float* q1 = &ha1.x;
        const float* r0 = &hb0.x; const float* r1 = &hb1.x;
#pragma unroll
        for (int j = 0; j < 4; j++) {
            *(uint32_t*)&hs[(h_n0 + j) * SK + h_kk0] = pack_bf16(q0[j], q1[j]);
            *(uint32_t*)&hs[(h_n0 + j) * SK + h_kk1] = pack_bf16(r0[j], r1[j]);
            h2 += q0[j]*q0[j] + q1[j]*q1[j] + r0[j]*r0[j] + r1[j]*r1[j];
        }
    };

    auto compute = [&](int buf) {
        const __nv_bfloat16* fs = Fs[buf];
        const __nv_bfloat16* hs = Hs[buf];
#pragma unroll
        for (int ks = 0; ks < BK; ks += 16) {
            uint32_t a[2][4], b[4][2];
#pragma unroll
            for (int mi = 0; mi < 2; mi++) {
                const __nv_bfloat16* p = &fs[(wm + mi * 16 + g) * SK + ks + 2 * t];
                a[mi][0] = *(const uint32_t*)(p);
                a[mi][1] = *(const uint32_t*)(p + 8 * SK);
                a[mi][2] = *(const uint32_t*)(p + 8);
                a[mi][3] = *(const uint32_t*)(p + 8 * SK + 8);
            }
#pragma unroll
            for (int ni = 0; ni < 4; ni++) {
                const __nv_bfloat16* p = &hs[(wn + ni * 8 + g) * SK + ks + 2 * t];
                b[ni][0] = *(const uint32_t*)(p);
                b[ni][1] = *(const uint32_t*)(p + 8);
            }
#pragma unroll
            for (int mi = 0; mi < 2; mi++)
#pragma unroll
                for (int ni = 0; ni < 4; ni++) {
                    asm volatile(
                        "mma.sync.aligned.m16n8k16.row.col.f32.bf16.bf16.f32 "
                        "{%0,%1,%2,%3}, {%4,%5,%6,%7}, {%8,%9}, {%0,%1,%2,%3};\n"
                        : "+f"(acc[mi][ni][0]), "+f"(acc[mi][ni][1]),
                          "+f"(acc[mi][ni][2]), "+f"(acc[mi][ni][3])
                        : "r"(a[mi][0]), "r"(a[mi][1]), "r"(a[mi][2]), "r"(a[mi][3]),
                          "r"(b[ni][0]), "r"(b[ni][1]));
                }
        }
    };

    // ---- round-1 pipeline: double buffer, register prefetch distance 1 ----
    gload(nb0);
    sstore(0);
    __syncthreads();

#pragma unroll 1
    for (int it = 0; it < ITERS; ++it) {
        int buf = it & 1;
        if (it + 1 < ITERS) gload(nb0 + (it + 1) * BK);
        compute(buf);
        if (it + 1 < ITERS) sstore(buf ^ 1);
        __syncthreads();
    }

    // ---- epilogue: packed float2 L2 atomics into partial G ----
#pragma unroll
    for (int mi = 0; mi < 2; mi++)
#pragma unroll
        for (int ni = 0; ni < 4; ni++) {
            int row = wm + mi * 16 + g;
            int col = d0 + wn + ni * 8 + 2 * t;
            atomicAdd((float2*)&g_partial[row * DDIM + col],
                      make_float2(acc[mi][ni][0], acc[mi][ni][1]));
            atomicAdd((float2*)&g_partial[(row + 8) * DDIM + col],
                      make_float2(acc[mi][ni][2], acc[mi][ni][3]));
        }

    // block-reduce h2, one atomic per CTA
#pragma unroll
    for (int o = 16; o > 0; o >>= 1) h2 += __shfl_xor_sync(0xffffffffu, h2, o);
    if (lane == 0) redbuf[wid] = h2;
    __syncthreads();
    if (tid == 0) {
        float s = 0.f;
#pragma unroll
        for (int w = 0; w < 8; w++) s += redbuf[w];
        atomicAdd(&g_h2sum, s);
    }

    // ---- last-CTA finalize: square-sum G, write scalar, reset state ----
    __threadfence();
    if (tid == 0) s_ticket = atomicAdd(&g_count, 1u);
    __syncthreads();
    if (s_ticket != NCTAS - 1) return;

    double s = 0.0;
    for (int i = tid; i < KCL * DDIM; i += 256) {
        float v = __ldcg(&g_partial[i]);
        s += (double)v * (double)v;
        g_partial[i] = 0.f;                 // re-zero for next graph replay
    }
#pragma unroll
    for (int o = 16; o > 0; o >>= 1) s += __shfl_xor_sync(0xffffffffu, s, o);
    if (lane == 0) sb[wid] = s;
    __syncthreads();
    if (tid == 0) {
        double tot = 0.0;
#pragma unroll
        for (int w = 0; w < 8; w++) tot += sb[w];
        float h2tot = __ldcg(&g_h2sum);
        out[0] = (float)((double)h2tot - tot);
        g_h2sum = 0.f;
        g_count = 0u;
    }
}

extern "C" void kernel_launch(void* const* d_in, const int* in_sizes, int n_in,
                              void* d_out, int out_size) {
    const float* Hp;
    const float* Fp;
    if (in_sizes[0] == NTOT * DDIM) {
        Hp = (const float*)d_in[0];
        Fp = (const float*)d_in[1];
    } else {
        Hp = (const float*)d_in[1];
        Fp = (const float*)d_in[0];
    }

    dim3 grid(DTILES, NCHUNKS);
    k_fused<<<grid, 256>>>(Hp, Fp, (float*)d_out);
}